// round 2
// baseline (speedup 1.0000x reference)
#include <cuda_runtime.h>
#include <math.h>

// Problem constants
#define B   4
#define C   64
#define H   128
#define W   128
#define G   8
#define CPG 8
#define NPT 9          // taps per kernel
#define PIX (H*W)      // 16384

// Scratch (static device memory; no allocation allowed)
__device__ __align__(16) float g_xt[B*G*PIX*CPG];      // anchor transposed (b,g,h,w,c)
__device__ __align__(16) float g_off[B*G*PIX*28];      // per-pixel: 18 offsets + 9 sigmoid(mask), stride 28
__device__ __align__(16) float g_target[B*C*PIX];      // deformable conv output
__device__ __align__(16) float g_mid[B*C*PIX];         // conv1 output

// ---------------------------------------------------------------------------
// Kernel 1: fused offset-conv (18ch) + mask-conv (9ch) + sigmoid, per group.
// grid (W/16, H/16, B*G), block (16,16)
// ---------------------------------------------------------------------------
__global__ __launch_bounds__(256)
void offset_mask_conv(const float* __restrict__ o,
                      const float* __restrict__ pw, const float* __restrict__ pb,
                      const float* __restrict__ mw, const float* __restrict__ mb)
{
    __shared__ float tsm[CPG * 18 * 18];   // input tile (8ch, 18x18)
    __shared__ float wsm[72 * 27];         // weights [(c*9+k)][27]
    __shared__ float bsm[27];

    const int tx = threadIdx.x, ty = threadIdx.y;
    const int tid = ty * 16 + tx;
    const int bg = blockIdx.z;
    const int b = bg >> 3, g = bg & 7;
    const int row0 = blockIdx.y * 16, col0 = blockIdx.x * 16;

    // load weights: wsm[(c*9+k)*27 + oc]
    for (int idx = tid; idx < 72 * 27; idx += 256) {
        int ck = idx / 27, oc = idx % 27;
        int c = ck / 9, k = ck % 9;
        float v;
        if (oc < 18) v = pw[((g * 18 + oc) * CPG + c) * 9 + k];
        else         v = mw[((g * 9 + (oc - 18)) * CPG + c) * 9 + k];
        wsm[idx] = v;
    }
    if (tid < 27) bsm[tid] = (tid < 18) ? pb[g * 18 + tid] : mb[g * 9 + (tid - 18)];

    // load input tile (18x18 with zero pad) for 8 channels
    const float* src = o + ((size_t)(b * C + g * CPG)) * PIX;
    for (int idx = tid; idx < CPG * 324; idx += 256) {
        int c = idx / 324, rem = idx % 324;
        int rr = rem / 18, cc = rem % 18;
        int gy = row0 + rr - 1, gx = col0 + cc - 1;
        float v = 0.f;
        if (gy >= 0 && gy < H && gx >= 0 && gx < W)
            v = src[c * PIX + gy * W + gx];
        tsm[idx] = v;
    }
    __syncthreads();

    float acc[27];
#pragma unroll
    for (int oc = 0; oc < 27; ++oc) acc[oc] = bsm[oc];

#pragma unroll
    for (int c = 0; c < CPG; ++c) {
#pragma unroll
        for (int ky = 0; ky < 3; ++ky) {
#pragma unroll
            for (int kx = 0; kx < 3; ++kx) {
                float xv = tsm[c * 324 + (ty + ky) * 18 + (tx + kx)];
                const float* wr = wsm + (c * 9 + ky * 3 + kx) * 27;
#pragma unroll
                for (int oc = 0; oc < 27; ++oc)
                    acc[oc] = fmaf(xv, wr[oc], acc[oc]);
            }
        }
    }

    const int y = row0 + ty, x = col0 + tx;
    float* op = g_off + ((size_t)bg * PIX + y * W + x) * 28;
#pragma unroll
    for (int oc = 0; oc < 18; ++oc) op[oc] = acc[oc];
#pragma unroll
    for (int oc = 18; oc < 27; ++oc) op[oc] = 1.f / (1.f + expf(-acc[oc]));
}

// ---------------------------------------------------------------------------
// Kernel 2: transpose anchor to channel-innermost (b,g,h,w,c)
// ---------------------------------------------------------------------------
__global__ __launch_bounds__(256)
void transpose_anchor(const float* __restrict__ anchor)
{
    int t = blockIdx.x * 256 + threadIdx.x;          // 0 .. B*G*PIX-1
    if (t >= B * G * PIX) return;
    int pix = t & (PIX - 1);
    int bg = t >> 14;
    int b = bg >> 3, g = bg & 7;
    const float* src = anchor + ((size_t)(b * C + g * CPG)) * PIX + pix;
#pragma unroll
    for (int c = 0; c < CPG; ++c)
        g_xt[(size_t)t * CPG + c] = src[c * PIX];
}

// ---------------------------------------------------------------------------
// Kernel 3: deformable bilinear sampling + modulation + group 3x3 "conv"
// grid (PIX/256, B*G), block 256. One thread = one pixel, all 8 out chans.
// ---------------------------------------------------------------------------
__global__ __launch_bounds__(256)
void deform_kernel(const float* __restrict__ cw)
{
    __shared__ float cw_s[NPT * CPG * CPG];  // [n][c][oc]

    const int tid = threadIdx.x;
    const int bg = blockIdx.y;
    const int b = bg >> 3, g = bg & 7;

    // load group conv weights, reorder to [n][c][oc]
    for (int idx = tid; idx < NPT * 64; idx += 256) {
        int n = idx / 64, rem = idx % 64;
        int c = rem / 8, oc = rem % 8;
        cw_s[idx] = cw[(((g * CPG + oc) * CPG + c) * NPT) + n];
    }
    __syncthreads();

    const int pixel = blockIdx.x * 256 + tid;
    const int i = pixel >> 7, j = pixel & (W - 1);

    // load the 27 per-pixel offset/mask values (stride 28, 16B aligned)
    float offv[28];
    const float4* op4 = (const float4*)(g_off + ((size_t)bg * PIX + pixel) * 28);
#pragma unroll
    for (int q = 0; q < 7; ++q) *(((float4*)offv) + q) = op4[q];

    const float4* xt4 = (const float4*)(g_xt + (size_t)bg * PIX * CPG);

    float acc[8];
#pragma unroll
    for (int oc = 0; oc < 8; ++oc) acc[oc] = 0.f;

#pragma unroll
    for (int n = 0; n < NPT; ++n) {
        const int pnx = n / 3 - 1, pny = n % 3 - 1;
        float px = (float)(i + 1 + pnx) + offv[n];
        float py = (float)(j + 1 + pny) + offv[NPT + n];
        float m  = offv[18 + n];

        float fx = floorf(px), fy = floorf(py);
        float qxl = fminf(fmaxf(fx,       0.f), (float)(H - 1));
        float qxr = fminf(fmaxf(fx + 1.f, 0.f), (float)(H - 1));
        float qyl = fminf(fmaxf(fy,       0.f), (float)(W - 1));
        float qyr = fminf(fmaxf(fy + 1.f, 0.f), (float)(W - 1));
        float pxc = fminf(fmaxf(px, 0.f), (float)(H - 1));
        float pyc = fminf(fmaxf(py, 0.f), (float)(W - 1));

        float glt = (1.f + (qxl - pxc)) * (1.f + (qyl - pyc));
        float grb = (1.f - (qxr - pxc)) * (1.f - (qyr - pyc));
        float glb = (1.f + (qxl - pxc)) * (1.f - (qyr - pyc));
        float grt = (1.f - (qxr - pxc)) * (1.f + (qyl - pyc));

        int ixl = (int)qxl, ixr = (int)qxr, iyl = (int)qyl, iyr = (int)qyr;

        const float4* pa = xt4 + (((ixl << 7) + iyl) << 1);  // lt
        const float4* pb_ = xt4 + (((ixr << 7) + iyr) << 1); // rb
        const float4* pc = xt4 + (((ixl << 7) + iyr) << 1);  // lb
        const float4* pd = xt4 + (((ixr << 7) + iyl) << 1);  // rt

        float av[8], bv[8], cv[8], dv[8];
        *(float4*)&av[0] = pa[0];  *(float4*)&av[4] = pa[1];
        *(float4*)&bv[0] = pb_[0]; *(float4*)&bv[4] = pb_[1];
        *(float4*)&cv[0] = pc[0];  *(float4*)&cv[4] = pc[1];
        *(float4*)&dv[0] = pd[0];  *(float4*)&dv[4] = pd[1];

        const float* wn = cw_s + n * 64;
#pragma unroll
        for (int c = 0; c < CPG; ++c) {
            float vc = fmaf(glt, av[c], fmaf(grb, bv[c], fmaf(glb, cv[c], grt * dv[c]))) * m;
            const float* wr = wn + c * 8;
#pragma unroll
            for (int oc = 0; oc < 8; ++oc)
                acc[oc] = fmaf(vc, wr[oc], acc[oc]);
        }
    }

    float* tp = g_target + ((size_t)(b * C + g * CPG)) * PIX + pixel;
#pragma unroll
    for (int oc = 0; oc < 8; ++oc) tp[oc * PIX] = acc[oc];
}

// ---------------------------------------------------------------------------
// Kernels 4/5: 3x3 conv, pad 1. MODE 0: in = cat(g_target, anchor) 128ch,
// writes g_mid (device-global — NOT passed from host!).
// MODE 1: in = g_mid 64ch, writes param out with +g_target residual.
// grid (W/32, H/8, B), block 256. Thread = 4 px * 16 oc.
// ---------------------------------------------------------------------------
template <int MODE>
__global__ __launch_bounds__(256)
void conv3x3_kernel(const float* __restrict__ anchor,
                    const float* __restrict__ wgt,
                    const float* __restrict__ bias,
                    float* __restrict__ out)
{
    constexpr int CIN = (MODE == 0) ? 128 : 64;
    __shared__ float tsm[10 * 34];
    __shared__ float wsm[64 * 9];
    __shared__ float bsm[64];

    const int tid = threadIdx.x;
    const int b = blockIdx.z;
    const int row0 = blockIdx.y * 8;
    const int col0 = blockIdx.x * 32;
    const int ocg = tid >> 6;        // 0..3 -> 16 ocs
    const int pq = tid & 63;
    const int r = pq >> 3;           // 0..7
    const int c0 = (pq & 7) * 4;     // 0,4,...,28

    if (tid < 64) bsm[tid] = bias[tid];
    __syncthreads();

    float acc[16][4];
#pragma unroll
    for (int q = 0; q < 16; ++q) {
        float bv = bsm[ocg * 16 + q];
#pragma unroll
        for (int p = 0; p < 4; ++p) acc[q][p] = bv;
    }

    for (int c = 0; c < CIN; ++c) {
        const float* src;
        if (MODE == 0)
            src = (c < 64) ? (g_target + ((size_t)(b * C + c)) * PIX)
                           : (anchor + ((size_t)(b * C + (c - 64))) * PIX);
        else
            src = g_mid + ((size_t)(b * C + c)) * PIX;

        __syncthreads();
        for (int idx = tid; idx < 340; idx += 256) {
            int rr = idx / 34, cc = idx % 34;
            int gy = row0 + rr - 1, gx = col0 + cc - 1;
            float v = 0.f;
            if (gy >= 0 && gy < H && gx >= 0 && gx < W)
                v = __ldg(src + gy * W + gx);
            tsm[idx] = v;
        }
        for (int idx = tid; idx < 576; idx += 256) {
            int oo = idx / 9, k = idx % 9;
            wsm[idx] = __ldg(wgt + (oo * CIN + c) * 9 + k);
        }
        __syncthreads();

#pragma unroll
        for (int ky = 0; ky < 3; ++ky) {
#pragma unroll
            for (int kx = 0; kx < 3; ++kx) {
                float xv[4];
#pragma unroll
                for (int p = 0; p < 4; ++p)
                    xv[p] = tsm[(r + ky) * 34 + c0 + p + kx];
#pragma unroll
                for (int q = 0; q < 16; ++q) {
                    float wv = wsm[(ocg * 16 + q) * 9 + ky * 3 + kx];
#pragma unroll
                    for (int p = 0; p < 4; ++p)
                        acc[q][p] = fmaf(wv, xv[p], acc[q][p]);
                }
            }
        }
    }

    const int y = row0 + r;
#pragma unroll
    for (int q = 0; q < 16; ++q) {
        int oc = ocg * 16 + q;
        size_t base = ((size_t)(b * C + oc)) * PIX + y * W + col0 + c0;
        if (MODE == 1) {
            const float* rp = g_target + base;
#pragma unroll
            for (int p = 0; p < 4; ++p) out[base + p] = acc[q][p] + rp[p];
        } else {
            // write to the device-global scratch directly (do NOT take the
            // address of a __device__ symbol from host code!)
            float* mp = g_mid + base;
#pragma unroll
            for (int p = 0; p < 4; ++p) mp[p] = acc[q][p];
        }
    }
}

// ---------------------------------------------------------------------------
extern "C" void kernel_launch(void* const* d_in, const int* in_sizes, int n_in,
                              void* d_out, int out_size)
{
    const float* o      = (const float*)d_in[0];
    const float* anchor = (const float*)d_in[1];
    const float* pw     = (const float*)d_in[2];
    const float* pb     = (const float*)d_in[3];
    const float* mw     = (const float*)d_in[4];
    const float* mb     = (const float*)d_in[5];
    const float* cw     = (const float*)d_in[6];
    const float* w1     = (const float*)d_in[7];
    const float* b1     = (const float*)d_in[8];
    const float* w2     = (const float*)d_in[9];
    const float* b2     = (const float*)d_in[10];
    float* out = (float*)d_out;

    offset_mask_conv<<<dim3(W / 16, H / 16, B * G), dim3(16, 16)>>>(o, pw, pb, mw, mb);
    transpose_anchor<<<(B * G * PIX) / 256, 256>>>(anchor);
    deform_kernel<<<dim3(PIX / 256, B * G), 256>>>(cw);

    conv3x3_kernel<0><<<dim3(W / 32, H / 8, B), 256>>>(anchor, w1, b1, nullptr);
    conv3x3_kernel<1><<<dim3(W / 32, H / 8, B), 256>>>(anchor, w2, b2, out);
}

// round 3
// speedup vs baseline: 1.6159x; 1.6159x over previous
#include <cuda_runtime.h>
#include <math.h>

// Problem constants
#define B   4
#define C   64
#define H   128
#define W   128
#define G   8
#define CPG 8
#define NPT 9
#define PIX (H*W)

typedef unsigned long long u64;

// Scratch (static device memory)
__device__ __align__(16) float g_xt[B*G*PIX*CPG];
__device__ __align__(16) float g_off[B*G*PIX*28];
__device__ __align__(16) float g_target[B*C*PIX];
__device__ __align__(16) float g_mid[B*C*PIX];
__device__ __align__(16) float g_wt1[128*9*64];   // [cin][k][oc]
__device__ __align__(16) float g_wt2[64*9*64];    // [cin][k][oc]

#define FMA2(acc, a, b) asm("fma.rn.f32x2 %0, %1, %2, %0;" : "+l"(acc) : "l"(a), "l"(b))
#define PACK_DUP(out, x) asm("mov.b64 %0, {%1, %1};" : "=l"(out) : "r"(__float_as_uint(x)))
#define UNPACK2(lo, hi, v) asm("mov.b64 {%0, %1}, %2;" : "=r"(lo), "=r"(hi) : "l"(v))

// ---------------------------------------------------------------------------
// Kernel 1: fused offset-conv (18ch) + mask-conv (9ch) + sigmoid, per group.
// ---------------------------------------------------------------------------
__global__ __launch_bounds__(256)
void offset_mask_conv(const float* __restrict__ o,
                      const float* __restrict__ pw, const float* __restrict__ pb,
                      const float* __restrict__ mw, const float* __restrict__ mb)
{
    __shared__ float tsm[CPG * 18 * 18];
    __shared__ float wsm[72 * 27];
    __shared__ float bsm[27];

    const int tx = threadIdx.x, ty = threadIdx.y;
    const int tid = ty * 16 + tx;
    const int bg = blockIdx.z;
    const int b = bg >> 3, g = bg & 7;
    const int row0 = blockIdx.y * 16, col0 = blockIdx.x * 16;

    for (int idx = tid; idx < 72 * 27; idx += 256) {
        int ck = idx / 27, oc = idx % 27;
        int c = ck / 9, k = ck % 9;
        float v;
        if (oc < 18) v = pw[((g * 18 + oc) * CPG + c) * 9 + k];
        else         v = mw[((g * 9 + (oc - 18)) * CPG + c) * 9 + k];
        wsm[idx] = v;
    }
    if (tid < 27) bsm[tid] = (tid < 18) ? pb[g * 18 + tid] : mb[g * 9 + (tid - 18)];

    const float* src = o + ((size_t)(b * C + g * CPG)) * PIX;
    for (int idx = tid; idx < CPG * 324; idx += 256) {
        int c = idx / 324, rem = idx % 324;
        int rr = rem / 18, cc = rem % 18;
        int gy = row0 + rr - 1, gx = col0 + cc - 1;
        float v = 0.f;
        if (gy >= 0 && gy < H && gx >= 0 && gx < W)
            v = src[c * PIX + gy * W + gx];
        tsm[idx] = v;
    }
    __syncthreads();

    float acc[27];
#pragma unroll
    for (int oc = 0; oc < 27; ++oc) acc[oc] = bsm[oc];

#pragma unroll
    for (int c = 0; c < CPG; ++c) {
#pragma unroll
        for (int ky = 0; ky < 3; ++ky) {
#pragma unroll
            for (int kx = 0; kx < 3; ++kx) {
                float xv = tsm[c * 324 + (ty + ky) * 18 + (tx + kx)];
                const float* wr = wsm + (c * 9 + ky * 3 + kx) * 27;
#pragma unroll
                for (int oc = 0; oc < 27; ++oc)
                    acc[oc] = fmaf(xv, wr[oc], acc[oc]);
            }
        }
    }

    const int y = row0 + ty, x = col0 + tx;
    float* op = g_off + ((size_t)bg * PIX + y * W + x) * 28;
#pragma unroll
    for (int oc = 0; oc < 18; ++oc) op[oc] = acc[oc];
#pragma unroll
    for (int oc = 18; oc < 27; ++oc) op[oc] = 1.f / (1.f + expf(-acc[oc]));
}

// ---------------------------------------------------------------------------
// Kernel 2: transpose anchor to channel-innermost + transpose conv weights
// ---------------------------------------------------------------------------
__global__ __launch_bounds__(256)
void transpose_anchor(const float* __restrict__ anchor,
                      const float* __restrict__ w1, const float* __restrict__ w2)
{
    int t = blockIdx.x * 256 + threadIdx.x;
    if (t < B * G * PIX) {
        int pix = t & (PIX - 1);
        int bg = t >> 14;
        int b = bg >> 3, g = bg & 7;
        const float* src = anchor + ((size_t)(b * C + g * CPG)) * PIX + pix;
#pragma unroll
        for (int c = 0; c < CPG; ++c)
            g_xt[(size_t)t * CPG + c] = src[c * PIX];
    }
    if (t < 64 * 128 * 9) {
        int oc = t / (128 * 9); int rem = t % (128 * 9); int c = rem / 9, k = rem % 9;
        g_wt1[(c * 9 + k) * 64 + oc] = w1[t];
    }
    if (t < 64 * 64 * 9) {
        int oc = t / (64 * 9); int rem = t % (64 * 9); int c = rem / 9, k = rem % 9;
        g_wt2[(c * 9 + k) * 64 + oc] = w2[t];
    }
}

// ---------------------------------------------------------------------------
// Kernel 3: deformable bilinear sampling + modulation + group 3x3 "conv"
// ---------------------------------------------------------------------------
__global__ __launch_bounds__(256)
void deform_kernel(const float* __restrict__ cw)
{
    __shared__ float cw_s[NPT * CPG * CPG];

    const int tid = threadIdx.x;
    const int bg = blockIdx.y;
    const int b = bg >> 3, g = bg & 7;

    for (int idx = tid; idx < NPT * 64; idx += 256) {
        int n = idx / 64, rem = idx % 64;
        int c = rem / 8, oc = rem % 8;
        cw_s[idx] = cw[(((g * CPG + oc) * CPG + c) * NPT) + n];
    }
    __syncthreads();

    const int pixel = blockIdx.x * 256 + tid;
    const int i = pixel >> 7, j = pixel & (W - 1);

    float offv[28];
    const float4* op4 = (const float4*)(g_off + ((size_t)bg * PIX + pixel) * 28);
#pragma unroll
    for (int q = 0; q < 7; ++q) *(((float4*)offv) + q) = op4[q];

    const float4* xt4 = (const float4*)(g_xt + (size_t)bg * PIX * CPG);

    float acc[8];
#pragma unroll
    for (int oc = 0; oc < 8; ++oc) acc[oc] = 0.f;

#pragma unroll
    for (int n = 0; n < NPT; ++n) {
        const int pnx = n / 3 - 1, pny = n % 3 - 1;
        float px = (float)(i + 1 + pnx) + offv[n];
        float py = (float)(j + 1 + pny) + offv[NPT + n];
        float m  = offv[18 + n];

        float fx = floorf(px), fy = floorf(py);
        float qxl = fminf(fmaxf(fx,       0.f), (float)(H - 1));
        float qxr = fminf(fmaxf(fx + 1.f, 0.f), (float)(H - 1));
        float qyl = fminf(fmaxf(fy,       0.f), (float)(W - 1));
        float qyr = fminf(fmaxf(fy + 1.f, 0.f), (float)(W - 1));
        float pxc = fminf(fmaxf(px, 0.f), (float)(H - 1));
        float pyc = fminf(fmaxf(py, 0.f), (float)(W - 1));

        float glt = (1.f + (qxl - pxc)) * (1.f + (qyl - pyc));
        float grb = (1.f - (qxr - pxc)) * (1.f - (qyr - pyc));
        float glb = (1.f + (qxl - pxc)) * (1.f - (qyr - pyc));
        float grt = (1.f - (qxr - pxc)) * (1.f + (qyl - pyc));

        int ixl = (int)qxl, ixr = (int)qxr, iyl = (int)qyl, iyr = (int)qyr;

        const float4* pa  = xt4 + (((ixl << 7) + iyl) << 1);
        const float4* pb_ = xt4 + (((ixr << 7) + iyr) << 1);
        const float4* pc  = xt4 + (((ixl << 7) + iyr) << 1);
        const float4* pd  = xt4 + (((ixr << 7) + iyl) << 1);

        float av[8], bv[8], cv[8], dv[8];
        *(float4*)&av[0] = pa[0];  *(float4*)&av[4] = pa[1];
        *(float4*)&bv[0] = pb_[0]; *(float4*)&bv[4] = pb_[1];
        *(float4*)&cv[0] = pc[0];  *(float4*)&cv[4] = pc[1];
        *(float4*)&dv[0] = pd[0];  *(float4*)&dv[4] = pd[1];

        const float* wn = cw_s + n * 64;
#pragma unroll
        for (int c = 0; c < CPG; ++c) {
            float vc = fmaf(glt, av[c], fmaf(grb, bv[c], fmaf(glb, cv[c], grt * dv[c]))) * m;
            const float* wr = wn + c * 8;
#pragma unroll
            for (int oc = 0; oc < 8; ++oc)
                acc[oc] = fmaf(vc, wr[oc], acc[oc]);
        }
    }

    float* tp = g_target + ((size_t)(b * C + g * CPG)) * PIX + pixel;
#pragma unroll
    for (int oc = 0; oc < 8; ++oc) tp[oc * PIX] = acc[oc];
}

// ---------------------------------------------------------------------------
// Kernels 4/5: register-tiled 3x3 conv with packed fma.rn.f32x2 (FFMA2).
// MODE 0: in = cat(g_target, anchor) 128ch -> g_mid.
// MODE 1: in = g_mid 64ch -> out (+ g_target residual).
// grid (W/32=4, H/4=32, B), block 256.
// Thread: 8 oc x 4 px (pairs of oc packed in f32x2).
// ---------------------------------------------------------------------------
#define TSTR 35          // tile row stride (conflict-free: (3r+c0+i)%32 distinct)
#define TILE_CH (6*TSTR) // 210

template <int MODE>
__global__ __launch_bounds__(256)
void conv3x3_v2(const float* __restrict__ anchor,
                const float* __restrict__ bias,
                float* __restrict__ out)
{
    constexpr int CIN = (MODE == 0) ? 128 : 64;
    __shared__ __align__(16) float tsm[4 * TILE_CH];  // 4 channels, 6x35 tile
    __shared__ __align__(16) float wsm[4 * 576];      // 4 channels, [k][64 oc]
    __shared__ __align__(16) float bsm[64];

    const int tid = threadIdx.x;
    const int b = blockIdx.z;
    const int y0 = blockIdx.y * 4;
    const int x0 = blockIdx.x * 32;
    const int ocg = tid >> 5;          // 0..7 -> oc0 = ocg*8
    const int pxg = tid & 31;
    const int r = pxg >> 3;            // 0..3
    const int c0 = (pxg & 7) * 4;      // 0..28

    if (tid < 64) bsm[tid] = bias[tid];
    __syncthreads();

    // init accumulators with bias (packed oc pairs)
    u64 acc2[4][4];
    {
        const u64* bp = (const u64*)bsm;
#pragma unroll
        for (int q = 0; q < 4; ++q) {
            u64 bv = bp[ocg * 4 + q];
#pragma unroll
            for (int p = 0; p < 4; ++p) acc2[q][p] = bv;
        }
    }

    const float* tgt_base = g_target + (size_t)b * C * PIX;
    const float* anc_base = anchor + (size_t)b * C * PIX;
    const float* mid_base = g_mid + (size_t)b * C * PIX;
    const float* wtr = (MODE == 0) ? g_wt1 : g_wt2;

    for (int cblk = 0; cblk < CIN; cblk += 4) {
        __syncthreads();
        // load transposed weights for 4 channels: 2304 floats = 576 float4
        {
            const float4* wg = (const float4*)(wtr + cblk * 576);
            float4* ws = (float4*)wsm;
            for (int i = tid; i < 576; i += 256) ws[i] = wg[i];
        }
        // load input tiles: 4 channels x 6 rows x 34 cols
        for (int i = tid; i < 4 * 204; i += 256) {
            int c = i / 204, rem = i % 204;
            int rr = rem / 34, cc2 = rem % 34;
            int gy = y0 - 1 + rr, gx = x0 - 1 + cc2;
            int ch = cblk + c;
            const float* src;
            if (MODE == 0)
                src = (ch < 64) ? (tgt_base + (size_t)ch * PIX)
                                : (anc_base + (size_t)(ch - 64) * PIX);
            else
                src = mid_base + (size_t)ch * PIX;
            float v = 0.f;
            if (gy >= 0 && gy < H && gx >= 0 && gx < W)
                v = __ldg(src + gy * W + gx);
            tsm[c * TILE_CH + rr * TSTR + cc2] = v;
        }
        __syncthreads();

#pragma unroll
        for (int c = 0; c < 4; ++c) {
            const float* tc = tsm + c * TILE_CH;
            const ulonglong2* wc = (const ulonglong2*)(wsm + c * 576);
#pragma unroll
            for (int ky = 0; ky < 3; ++ky) {
                u64 xb[6];
#pragma unroll
                for (int i = 0; i < 6; ++i) {
                    float xv = tc[(r + ky) * TSTR + c0 + i];
                    PACK_DUP(xb[i], xv);
                }
#pragma unroll
                for (int kx = 0; kx < 3; ++kx) {
                    int k = ky * 3 + kx;
                    ulonglong2 w01 = wc[k * 16 + ocg * 2];
                    ulonglong2 w23 = wc[k * 16 + ocg * 2 + 1];
                    u64 w2v[4] = {w01.x, w01.y, w23.x, w23.y};
#pragma unroll
                    for (int q = 0; q < 4; ++q) {
#pragma unroll
                        for (int p = 0; p < 4; ++p)
                            FMA2(acc2[q][p], w2v[q], xb[kx + p]);
                    }
                }
            }
        }
    }

    // unpack and store
    const int y = y0 + r;
#pragma unroll
    for (int q = 0; q < 4; ++q) {
        float lo[4], hi[4];
#pragma unroll
        for (int p = 0; p < 4; ++p) {
            unsigned int ulo, uhi;
            UNPACK2(ulo, uhi, acc2[q][p]);
            lo[p] = __uint_as_float(ulo);
            hi[p] = __uint_as_float(uhi);
        }
        int oc_lo = ocg * 8 + 2 * q;
        size_t base_lo = ((size_t)(b * C + oc_lo)) * PIX + y * W + x0 + c0;
        size_t base_hi = base_lo + PIX;
        if (MODE == 1) {
            const float4 rlo = *(const float4*)(g_target + base_lo);
            const float4 rhi = *(const float4*)(g_target + base_hi);
            *(float4*)(out + base_lo) = make_float4(lo[0]+rlo.x, lo[1]+rlo.y, lo[2]+rlo.z, lo[3]+rlo.w);
            *(float4*)(out + base_hi) = make_float4(hi[0]+rhi.x, hi[1]+rhi.y, hi[2]+rhi.z, hi[3]+rhi.w);
        } else {
            *(float4*)(g_mid + base_lo) = make_float4(lo[0], lo[1], lo[2], lo[3]);
            *(float4*)(g_mid + base_hi) = make_float4(hi[0], hi[1], hi[2], hi[3]);
        }
    }
}

// ---------------------------------------------------------------------------
extern "C" void kernel_launch(void* const* d_in, const int* in_sizes, int n_in,
                              void* d_out, int out_size)
{
    const float* o      = (const float*)d_in[0];
    const float* anchor = (const float*)d_in[1];
    const float* pw     = (const float*)d_in[2];
    const float* pb     = (const float*)d_in[3];
    const float* mw     = (const float*)d_in[4];
    const float* mb     = (const float*)d_in[5];
    const float* cw     = (const float*)d_in[6];
    const float* w1     = (const float*)d_in[7];
    const float* b1     = (const float*)d_in[8];
    const float* w2     = (const float*)d_in[9];
    const float* b2     = (const float*)d_in[10];
    float* out = (float*)d_out;

    offset_mask_conv<<<dim3(W / 16, H / 16, B * G), dim3(16, 16)>>>(o, pw, pb, mw, mb);
    transpose_anchor<<<(B * G * PIX + 255) / 256, 256>>>(anchor, w1, w2);
    deform_kernel<<<dim3(PIX / 256, B * G), 256>>>(cw);

    conv3x3_v2<0><<<dim3(W / 32, H / 4, B), 256>>>(anchor, b1, nullptr);
    conv3x3_v2<1><<<dim3(W / 32, H / 4, B), 256>>>(anchor, b2, out);
}

// round 4
// speedup vs baseline: 1.9589x; 1.2123x over previous
#include <cuda_runtime.h>
#include <math.h>

// Problem constants
#define B   4
#define C   64
#define H   128
#define W   128
#define G   8
#define CPG 8
#define NPT 9
#define PIX (H*W)

typedef unsigned long long u64;

// Scratch (static device memory)
__device__ __align__(16) float g_xt[B*G*PIX*CPG];
__device__ __align__(16) float g_off[B*G*PIX*28];
__device__ __align__(16) float g_target[B*C*PIX];
__device__ __align__(16) float g_mid[B*C*PIX];
__device__ __align__(16) float g_wt1[128*9*64];   // [cin][k][oc]
__device__ __align__(16) float g_wt2[64*9*64];    // [cin][k][oc]

#define FMA2(acc, a, b) asm("fma.rn.f32x2 %0, %1, %2, %0;" : "+l"(acc) : "l"(a), "l"(b))
#define PACK_DUP(out, x) asm("mov.b64 %0, {%1, %1};" : "=l"(out) : "r"(__float_as_uint(x)))
#define UNPACK2(lo, hi, v) asm("mov.b64 {%0, %1}, %2;" : "=r"(lo), "=r"(hi) : "l"(v))

__device__ __forceinline__ void cp_async16(unsigned smem_addr, const void* gptr) {
    asm volatile("cp.async.cg.shared.global [%0], [%1], 16;" :: "r"(smem_addr), "l"(gptr));
}
__device__ __forceinline__ void cp_commit() { asm volatile("cp.async.commit_group;"); }
__device__ __forceinline__ void cp_wait0()  { asm volatile("cp.async.wait_group 0;" ::: "memory"); }

// ---------------------------------------------------------------------------
// Kernel 1: fused offset-conv (18ch) + mask-conv (9ch) + sigmoid, per group.
// ---------------------------------------------------------------------------
__global__ __launch_bounds__(256)
void offset_mask_conv(const float* __restrict__ o,
                      const float* __restrict__ pw, const float* __restrict__ pb,
                      const float* __restrict__ mw, const float* __restrict__ mb)
{
    __shared__ float tsm[CPG * 18 * 18];
    __shared__ float wsm[72 * 27];
    __shared__ float bsm[27];

    const int tx = threadIdx.x, ty = threadIdx.y;
    const int tid = ty * 16 + tx;
    const int bg = blockIdx.z;
    const int b = bg >> 3, g = bg & 7;
    const int row0 = blockIdx.y * 16, col0 = blockIdx.x * 16;

    for (int idx = tid; idx < 72 * 27; idx += 256) {
        int ck = idx / 27, oc = idx % 27;
        int c = ck / 9, k = ck % 9;
        float v;
        if (oc < 18) v = pw[((g * 18 + oc) * CPG + c) * 9 + k];
        else         v = mw[((g * 9 + (oc - 18)) * CPG + c) * 9 + k];
        wsm[idx] = v;
    }
    if (tid < 27) bsm[tid] = (tid < 18) ? pb[g * 18 + tid] : mb[g * 9 + (tid - 18)];

    const float* src = o + ((size_t)(b * C + g * CPG)) * PIX;
    for (int idx = tid; idx < CPG * 324; idx += 256) {
        int c = idx / 324, rem = idx % 324;
        int rr = rem / 18, cc = rem % 18;
        int gy = row0 + rr - 1, gx = col0 + cc - 1;
        float v = 0.f;
        if (gy >= 0 && gy < H && gx >= 0 && gx < W)
            v = src[c * PIX + gy * W + gx];
        tsm[idx] = v;
    }
    __syncthreads();

    float acc[27];
#pragma unroll
    for (int oc = 0; oc < 27; ++oc) acc[oc] = bsm[oc];

#pragma unroll
    for (int c = 0; c < CPG; ++c) {
#pragma unroll
        for (int ky = 0; ky < 3; ++ky) {
#pragma unroll
            for (int kx = 0; kx < 3; ++kx) {
                float xv = tsm[c * 324 + (ty + ky) * 18 + (tx + kx)];
                const float* wr = wsm + (c * 9 + ky * 3 + kx) * 27;
#pragma unroll
                for (int oc = 0; oc < 27; ++oc)
                    acc[oc] = fmaf(xv, wr[oc], acc[oc]);
            }
        }
    }

    const int y = row0 + ty, x = col0 + tx;
    float* op = g_off + ((size_t)bg * PIX + y * W + x) * 28;
#pragma unroll
    for (int oc = 0; oc < 18; ++oc) op[oc] = acc[oc];
#pragma unroll
    for (int oc = 18; oc < 27; ++oc) op[oc] = 1.f / (1.f + expf(-acc[oc]));
}

// ---------------------------------------------------------------------------
// Kernel 2: transpose anchor to channel-innermost + transpose conv weights
// ---------------------------------------------------------------------------
__global__ __launch_bounds__(256)
void transpose_anchor(const float* __restrict__ anchor,
                      const float* __restrict__ w1, const float* __restrict__ w2)
{
    int t = blockIdx.x * 256 + threadIdx.x;
    if (t < B * G * PIX) {
        int pix = t & (PIX - 1);
        int bg = t >> 14;
        int b = bg >> 3, g = bg & 7;
        const float* src = anchor + ((size_t)(b * C + g * CPG)) * PIX + pix;
#pragma unroll
        for (int c = 0; c < CPG; ++c)
            g_xt[(size_t)t * CPG + c] = src[c * PIX];
    }
    if (t < 64 * 128 * 9) {
        int oc = t / (128 * 9); int rem = t % (128 * 9); int c = rem / 9, k = rem % 9;
        g_wt1[(c * 9 + k) * 64 + oc] = w1[t];
    }
    if (t < 64 * 64 * 9) {
        int oc = t / (64 * 9); int rem = t % (64 * 9); int c = rem / 9, k = rem % 9;
        g_wt2[(c * 9 + k) * 64 + oc] = w2[t];
    }
}

// ---------------------------------------------------------------------------
// Kernel 3: deformable bilinear sampling + modulation + group 3x3 "conv"
// ---------------------------------------------------------------------------
__global__ __launch_bounds__(256)
void deform_kernel(const float* __restrict__ cw)
{
    __shared__ float cw_s[NPT * CPG * CPG];

    const int tid = threadIdx.x;
    const int bg = blockIdx.y;
    const int b = bg >> 3, g = bg & 7;

    for (int idx = tid; idx < NPT * 64; idx += 256) {
        int n = idx / 64, rem = idx % 64;
        int c = rem / 8, oc = rem % 8;
        cw_s[idx] = cw[(((g * CPG + oc) * CPG + c) * NPT) + n];
    }
    __syncthreads();

    const int pixel = blockIdx.x * 256 + tid;
    const int i = pixel >> 7, j = pixel & (W - 1);

    float offv[28];
    const float4* op4 = (const float4*)(g_off + ((size_t)bg * PIX + pixel) * 28);
#pragma unroll
    for (int q = 0; q < 7; ++q) *(((float4*)offv) + q) = op4[q];

    const float4* xt4 = (const float4*)(g_xt + (size_t)bg * PIX * CPG);

    float acc[8];
#pragma unroll
    for (int oc = 0; oc < 8; ++oc) acc[oc] = 0.f;

#pragma unroll
    for (int n = 0; n < NPT; ++n) {
        const int pnx = n / 3 - 1, pny = n % 3 - 1;
        float px = (float)(i + 1 + pnx) + offv[n];
        float py = (float)(j + 1 + pny) + offv[NPT + n];
        float m  = offv[18 + n];

        float fx = floorf(px), fy = floorf(py);
        float qxl = fminf(fmaxf(fx,       0.f), (float)(H - 1));
        float qxr = fminf(fmaxf(fx + 1.f, 0.f), (float)(H - 1));
        float qyl = fminf(fmaxf(fy,       0.f), (float)(W - 1));
        float qyr = fminf(fmaxf(fy + 1.f, 0.f), (float)(W - 1));
        float pxc = fminf(fmaxf(px, 0.f), (float)(H - 1));
        float pyc = fminf(fmaxf(py, 0.f), (float)(W - 1));

        float glt = (1.f + (qxl - pxc)) * (1.f + (qyl - pyc));
        float grb = (1.f - (qxr - pxc)) * (1.f - (qyr - pyc));
        float glb = (1.f + (qxl - pxc)) * (1.f - (qyr - pyc));
        float grt = (1.f - (qxr - pxc)) * (1.f + (qyl - pyc));

        int ixl = (int)qxl, ixr = (int)qxr, iyl = (int)qyl, iyr = (int)qyr;

        const float4* pa  = xt4 + (((ixl << 7) + iyl) << 1);
        const float4* pb_ = xt4 + (((ixr << 7) + iyr) << 1);
        const float4* pc  = xt4 + (((ixl << 7) + iyr) << 1);
        const float4* pd  = xt4 + (((ixr << 7) + iyl) << 1);

        float av[8], bv[8], cv[8], dv[8];
        *(float4*)&av[0] = pa[0];  *(float4*)&av[4] = pa[1];
        *(float4*)&bv[0] = pb_[0]; *(float4*)&bv[4] = pb_[1];
        *(float4*)&cv[0] = pc[0];  *(float4*)&cv[4] = pc[1];
        *(float4*)&dv[0] = pd[0];  *(float4*)&dv[4] = pd[1];

        const float* wn = cw_s + n * 64;
#pragma unroll
        for (int c = 0; c < CPG; ++c) {
            float vc = fmaf(glt, av[c], fmaf(grb, bv[c], fmaf(glb, cv[c], grt * dv[c]))) * m;
            const float* wr = wn + c * 8;
#pragma unroll
            for (int oc = 0; oc < 8; ++oc)
                acc[oc] = fmaf(vc, wr[oc], acc[oc]);
        }
    }

    float* tp = g_target + ((size_t)(b * C + g * CPG)) * PIX + pixel;
#pragma unroll
    for (int oc = 0; oc < 8; ++oc) tp[oc * PIX] = acc[oc];
}

// ---------------------------------------------------------------------------
// Kernels 4/5: double-buffered register-tiled 3x3 conv, packed fma.rn.f32x2.
// MODE 0: in = cat(g_target, anchor) 128ch -> g_mid.
// MODE 1: in = g_mid 64ch -> out (+ g_target residual).
// grid (W/32=4, H/8=16, B) = 256 CTAs (single wave), block 256.
// Thread: 8 oc x 8 px. Channel blocks of 4, weights via cp.async,
// tile via LDG->reg->STS, 1 barrier per block.
// ---------------------------------------------------------------------------
#define TSTR 35            // tile row stride (bank-conflict-free)
#define TILE_CH (10*TSTR)  // 350 floats per channel (10 rows)
#define WBLK 2304          // weights per 4-ch block (4*9*64)

template <int MODE>
__global__ __launch_bounds__(256, 2)
void conv3x3_v3(const float* __restrict__ anchor,
                const float* __restrict__ bias,
                float* __restrict__ out)
{
    constexpr int CIN = (MODE == 0) ? 128 : 64;
    constexpr int NBLK = CIN / 4;
    __shared__ __align__(16) float tsm[2][4 * TILE_CH];
    __shared__ __align__(16) float wsm[2][WBLK];
    __shared__ __align__(16) float bsm[64];

    const int tid = threadIdx.x;
    const int b = blockIdx.z;
    const int y0 = blockIdx.y * 8;
    const int x0 = blockIdx.x * 32;
    const int ocg = tid >> 5;            // 0..7 -> oc0 = ocg*8
    const int pxg = tid & 31;
    const int r = pxg >> 2;              // 0..7
    const int c0 = (pxg & 3) * 8;        // 0,8,16,24

    if (tid < 64) bsm[tid] = bias[tid];

    const float* tgt_base = g_target + (size_t)b * C * PIX;
    const float* anc_base = anchor + (size_t)b * C * PIX;
    const float* mid_base = g_mid + (size_t)b * C * PIX;
    const float* wtr = (MODE == 0) ? g_wt1 : g_wt2;

    // Precompute per-thread tile-load slots (6 entries cover 4*340=1360)
    int t_valid[6], t_pix[6], t_smo[6], t_ch[6];
#pragma unroll
    for (int j = 0; j < 6; ++j) {
        int idx = tid + j * 256;
        int ok = idx < 1360;
        int c = idx / 340, rem = idx % 340;
        int rr = rem / 34, cc = rem % 34;
        int gy = y0 - 1 + rr, gx = x0 - 1 + cc;
        t_valid[j] = ok && gy >= 0 && gy < H && gx >= 0 && gx < W;
        t_pix[j] = gy * W + gx;
        t_smo[j] = c * TILE_CH + rr * TSTR + cc;
        t_ch[j] = c;
        if (!ok) { t_smo[j] = -1; }
    }

    // helper lambda: global src pointer for (block, local ch, pix)
    auto src_ptr = [&](int cblk, int c, int pix) -> const float* {
        int ch = cblk + c;
        if (MODE == 0)
            return (ch < 64) ? (tgt_base + (size_t)ch * PIX + pix)
                             : (anc_base + (size_t)(ch - 64) * PIX + pix);
        else
            return mid_base + (size_t)ch * PIX + pix;
    };

    // ---- prologue: fetch block 0 ----
    {
        const float4* wg = (const float4*)(wtr);
#pragma unroll
        for (int k = 0; k < 3; ++k) {
            int i = tid + k * 256;
            if (i < 576)
                cp_async16((unsigned)__cvta_generic_to_shared(&((float4*)wsm[0])[i]), &wg[i]);
        }
        cp_commit();
        float v[6];
#pragma unroll
        for (int j = 0; j < 6; ++j)
            v[j] = t_valid[j] ? __ldg(src_ptr(0, t_ch[j], t_pix[j])) : 0.f;
#pragma unroll
        for (int j = 0; j < 6; ++j)
            if (t_smo[j] >= 0) tsm[0][t_smo[j]] = v[j];
        cp_wait0();
    }
    __syncthreads();

    // init accumulators with bias (packed oc pairs)
    u64 acc2[4][8];
    {
        const u64* bp = (const u64*)bsm;
#pragma unroll
        for (int q = 0; q < 4; ++q) {
            u64 bv = bp[ocg * 4 + q];
#pragma unroll
            for (int p = 0; p < 8; ++p) acc2[q][p] = bv;
        }
    }

    for (int blk = 0; blk < NBLK; ++blk) {
        const int p = blk & 1;
        const int nblk = (blk + 1 < NBLK) ? blk + 1 : blk;
        const int ncblk = nblk * 4;

        // prefetch weights for next block (async)
        {
            const float4* wg = (const float4*)(wtr + ncblk * 576);
#pragma unroll
            for (int k = 0; k < 3; ++k) {
                int i = tid + k * 256;
                if (i < 576)
                    cp_async16((unsigned)__cvta_generic_to_shared(&((float4*)wsm[p ^ 1])[i]), &wg[i]);
            }
            cp_commit();
        }
        // prefetch tile for next block into registers
        float v[6];
#pragma unroll
        for (int j = 0; j < 6; ++j)
            v[j] = t_valid[j] ? __ldg(src_ptr(ncblk, t_ch[j], t_pix[j])) : 0.f;

        // ---- compute block blk ----
#pragma unroll
        for (int c = 0; c < 4; ++c) {
            const float* tc = tsm[p] + c * TILE_CH;
            const ulonglong2* wc = (const ulonglong2*)(wsm[p] + c * 576);
#pragma unroll
            for (int ky = 0; ky < 3; ++ky) {
                u64 xb[10];
#pragma unroll
                for (int i = 0; i < 10; ++i) {
                    float xv = tc[(r + ky) * TSTR + c0 + i];
                    PACK_DUP(xb[i], xv);
                }
#pragma unroll
                for (int kx = 0; kx < 3; ++kx) {
                    int k = ky * 3 + kx;
                    ulonglong2 w01 = wc[k * 16 + ocg * 2];
                    ulonglong2 w23 = wc[k * 16 + ocg * 2 + 1];
                    u64 w2v[4] = {w01.x, w01.y, w23.x, w23.y};
#pragma unroll
                    for (int q = 0; q < 4; ++q) {
#pragma unroll
                        for (int pp = 0; pp < 8; ++pp)
                            FMA2(acc2[q][pp], w2v[q], xb[kx + pp]);
                    }
                }
            }
        }

        // stage next tile into the other buffer
#pragma unroll
        for (int j = 0; j < 6; ++j)
            if (t_smo[j] >= 0) tsm[p ^ 1][t_smo[j]] = v[j];
        cp_wait0();
        __syncthreads();
    }

    // unpack and store
    const int y = y0 + r;
#pragma unroll
    for (int q = 0; q < 4; ++q) {
        float lo[8], hi[8];
#pragma unroll
        for (int pp = 0; pp < 8; ++pp) {
            unsigned int ulo, uhi;
            UNPACK2(ulo, uhi, acc2[q][pp]);
            lo[pp] = __uint_as_float(ulo);
            hi[pp] = __uint_as_float(uhi);
        }
        int oc_lo = ocg * 8 + 2 * q;
        size_t base_lo = ((size_t)(b * C + oc_lo)) * PIX + y * W + x0 + c0;
        size_t base_hi = base_lo + PIX;
        if (MODE == 1) {
#pragma unroll
            for (int h = 0; h < 2; ++h) {
                const float4 rlo = *(const float4*)(g_target + base_lo + h * 4);
                const float4 rhi = *(const float4*)(g_target + base_hi + h * 4);
                *(float4*)(out + base_lo + h * 4) =
                    make_float4(lo[h*4]+rlo.x, lo[h*4+1]+rlo.y, lo[h*4+2]+rlo.z, lo[h*4+3]+rlo.w);
                *(float4*)(out + base_hi + h * 4) =
                    make_float4(hi[h*4]+rhi.x, hi[h*4+1]+rhi.y, hi[h*4+2]+rhi.z, hi[h*4+3]+rhi.w);
            }
        } else {
#pragma unroll
            for (int h = 0; h < 2; ++h) {
                *(float4*)(g_mid + base_lo + h * 4) =
                    make_float4(lo[h*4], lo[h*4+1], lo[h*4+2], lo[h*4+3]);
                *(float4*)(g_mid + base_hi + h * 4) =
                    make_float4(hi[h*4], hi[h*4+1], hi[h*4+2], hi[h*4+3]);
            }
        }
    }
}

// ---------------------------------------------------------------------------
extern "C" void kernel_launch(void* const* d_in, const int* in_sizes, int n_in,
                              void* d_out, int out_size)
{
    const float* o      = (const float*)d_in[0];
    const float* anchor = (const float*)d_in[1];
    const float* pw     = (const float*)d_in[2];
    const float* pb     = (const float*)d_in[3];
    const float* mw     = (const float*)d_in[4];
    const float* mb     = (const float*)d_in[5];
    const float* cw     = (const float*)d_in[6];
    const float* w1     = (const float*)d_in[7];
    const float* b1     = (const float*)d_in[8];
    const float* w2     = (const float*)d_in[9];
    const float* b2     = (const float*)d_in[10];
    float* out = (float*)d_out;

    offset_mask_conv<<<dim3(W / 16, H / 16, B * G), dim3(16, 16)>>>(o, pw, pb, mw, mb);
    transpose_anchor<<<(B * G * PIX + 255) / 256, 256>>>(anchor, w1, w2);
    deform_kernel<<<dim3(PIX / 256, B * G), 256>>>(cw);

    conv3x3_v3<0><<<dim3(W / 32, H / 8, B), 256>>>(anchor, b1, nullptr);
    conv3x3_v3<1><<<dim3(W / 32, H / 8, B), 256>>>(anchor, b2, out);
}